// round 1
// baseline (speedup 1.0000x reference)
#include <cuda_runtime.h>
#include <cuda_bf16.h>

#define FULL 0xffffffffu

static __device__ __forceinline__ unsigned long long pk2(float lo, float hi) {
    unsigned long long r;
    asm("mov.b64 %0, {%1,%2};" : "=l"(r) : "f"(lo), "f"(hi));
    return r;
}
static __device__ __forceinline__ void upk2(unsigned long long v, float& lo, float& hi) {
    asm("mov.b64 {%0,%1}, %2;" : "=f"(lo), "=f"(hi) : "l"(v));
}
static __device__ __forceinline__ unsigned long long fma2(unsigned long long a,
                                                          unsigned long long b,
                                                          unsigned long long c) {
    unsigned long long d;
    asm("fma.rn.f32x2 %0,%1,%2,%3;" : "=l"(d) : "l"(a), "l"(b), "l"(c));
    return d;
}
static __device__ __forceinline__ unsigned long long add2(unsigned long long a,
                                                           unsigned long long b) {
    unsigned long long d;
    asm("add.rn.f32x2 %0,%1,%2;" : "=l"(d) : "l"(a), "l"(b));
    return d;
}
static __device__ __forceinline__ unsigned long long mul2(unsigned long long a,
                                                           unsigned long long b) {
    unsigned long long d;
    asm("mul.rn.f32x2 %0,%1,%2;" : "=l"(d) : "l"(a), "l"(b));
    return d;
}

static constexpr int Bb = 256;
static constexpr int Tt = 2048;
static constexpr int Dd = 64;

// One warp (one block of 32 threads) per batch element.
// Lane l owns CRF state columns 2l and 2l+1 (packed f32x2).
// State kept in LINEAR domain with power-of-two renormalization:
//   v_t[d] = exp(alpha_t[d]) * 2^{-K_t},   K accumulated in integer ktot.
__global__ __launch_bounds__(32) void crf_forward_kernel(
    const float* __restrict__ p,       // [B,T,D]
    const int*   __restrict__ y,       // [B,T,D] one-hot
    const int*   __restrict__ mask,    // [B,T]   1 = padding
    const float* __restrict__ trans,   // [D,D]
    float*       __restrict__ out)     // [B]
{
    const int b = blockIdx.x;
    const int l = threadIdx.x;

    // double-buffered duplicated state: sh[buf + c] = {v[c], v[c]}
    __shared__ unsigned long long sh[128];

    // ---- sequence length L = T - sum(mask[b,:])  (mask is a suffix of 1s) ----
    const int4* m4 = reinterpret_cast<const int4*>(mask + (size_t)b * Tt);
    int s = 0;
#pragma unroll
    for (int j = 0; j < 16; j++) {
        int4 v = m4[l + 32 * j];
        s += v.x + v.y + v.z + v.w;
    }
#pragma unroll
    for (int o = 16; o > 0; o >>= 1) s += __shfl_xor_sync(FULL, s, o);
    const int L = Tt - s;

    // ---- expT columns (2l, 2l+1) for all 64 rows, packed in registers ----
    unsigned long long eT[64];
#pragma unroll
    for (int j = 0; j < 64; j++) {
        float2 tv = reinterpret_cast<const float2*>(trans)[j * 32 + l];
        eT[j] = pk2(__expf(tv.x), __expf(tv.y));
    }

    const float2* pB = reinterpret_cast<const float2*>(p + (size_t)b * Tt * Dd);
    const int2*   yB = reinterpret_cast<const int2*>(y + (size_t)b * Tt * Dd);

    // ---- t = 0 init ----
    float2 p0 = pB[l];
    int2   y0 = yB[l];
    float s1 = 0.f;
    if (y0.x) s1 += p0.x;
    if (y0.y) s1 += p0.y;
    unsigned bx = __ballot_sync(FULL, y0.x != 0);
    unsigned by = __ballot_sync(FULL, y0.y != 0);
    int prev = bx ? 2 * (__ffs(bx) - 1) : 2 * (__ffs(by) - 1) + 1;

    float vx = __expf(p0.x);
    float vy = __expf(p0.y);
    float s2 = 0.f;
    int ktot = 0;
    int kx = 0;
    if (l == 0) kx = (int)((__float_as_uint(vx) >> 23) & 255) - 127;

    sh[2 * l]     = pk2(vx, vx);
    sh[2 * l + 1] = pk2(vy, vy);
    __syncwarp();

    // prefetch t = 1
    int tn = (1 < L) ? 1 : 0;
    float2 pt = pB[tn * 32 + l];
    int2   yt = yB[tn * 32 + l];

    for (int t = 1; t < L; t++) {
        const int buf  = (t & 1) * 64;  // write buffer this iteration
        const int rbuf = buf ^ 64;      // read buffer (written last iteration)

        // broadcast stale exponent correction, fold into exp(p_t)
        int k = __shfl_sync(FULL, kx, 0);
        ktot += k;
        float sc = __uint_as_float((unsigned)(127 - k) << 23);  // 2^{-k}
        unsigned long long ep2 = pk2(__expf(pt.x) * sc, __expf(pt.y) * sc);

        // emission / transition scores from one-hot y
        if (yt.x) s1 += pt.x;
        if (yt.y) s1 += pt.y;
        unsigned bbx = __ballot_sync(FULL, yt.x != 0);
        unsigned bby = __ballot_sync(FULL, yt.y != 0);
        int cur = bbx ? 2 * (__ffs(bbx) - 1) : 2 * (__ffs(bby) - 1) + 1;
        if (l == 0) s2 += __ldg(&trans[prev * 64 + cur]);
        prev = cur;

        // prefetch next timestep (clamped, harmless re-read on last iter)
        int tnx = (t + 1 < L) ? (t + 1) : t;
        float2 pn = pB[tnx * 32 + l];
        int2   yn = yB[tnx * 32 + l];

        // S[c] = sum_{d'} v[d'] * expT[d'][c]   (64 LDS.64 broadcast + 64 FFMA2)
        unsigned long long a0 = 0, a1 = 0, a2 = 0, a3 = 0;
#pragma unroll
        for (int j = 0; j < 64; j += 4) {
            a0 = fma2(sh[rbuf + j + 0], eT[j + 0], a0);
            a1 = fma2(sh[rbuf + j + 1], eT[j + 1], a1);
            a2 = fma2(sh[rbuf + j + 2], eT[j + 2], a2);
            a3 = fma2(sh[rbuf + j + 3], eT[j + 3], a3);
        }
        unsigned long long S  = add2(add2(a0, a1), add2(a2, a3));
        unsigned long long v2 = mul2(S, ep2);
        upk2(v2, vx, vy);

        if (l == 0) kx = (int)((__float_as_uint(vx) >> 23) & 255) - 127;

        sh[buf + 2 * l]     = pk2(vx, vx);
        sh[buf + 2 * l + 1] = pk2(vy, vy);
        __syncwarp();

        pt = pn;
        yt = yn;
    }

    // ---- finalize: logZ = log(sum v) + ktot*ln2 ----
    float sumv = vx + vy;
#pragma unroll
    for (int o = 16; o > 0; o >>= 1) {
        sumv += __shfl_xor_sync(FULL, sumv, o);
        s1   += __shfl_xor_sync(FULL, s1, o);
    }
    if (l == 0) {
        float logZ = logf(sumv) + (float)ktot * 0.6931471805599453f;
        out[b] = logZ - s1 - s2;
    }
}

extern "C" void kernel_launch(void* const* d_in, const int* in_sizes, int n_in,
                              void* d_out, int out_size) {
    const float* p     = (const float*)d_in[0];
    const int*   y     = (const int*)d_in[1];
    const int*   mask  = (const int*)d_in[2];
    const float* trans = (const float*)d_in[3];
    float* out = (float*)d_out;
    crf_forward_kernel<<<Bb, 32>>>(p, y, mask, trans, out);
}

// round 2
// speedup vs baseline: 1.6759x; 1.6759x over previous
#include <cuda_runtime.h>
#include <cuda_bf16.h>

#define FULL 0xffffffffu

static __device__ __forceinline__ unsigned long long pk2(float lo, float hi) {
    unsigned long long r;
    asm("mov.b64 %0, {%1,%2};" : "=l"(r) : "f"(lo), "f"(hi));
    return r;
}
static __device__ __forceinline__ void upk2(unsigned long long v, float& lo, float& hi) {
    asm("mov.b64 {%0,%1}, %2;" : "=f"(lo), "=f"(hi) : "l"(v));
}
static __device__ __forceinline__ unsigned long long fma2(unsigned long long a,
                                                          unsigned long long b,
                                                          unsigned long long c) {
    unsigned long long d;
    asm("fma.rn.f32x2 %0,%1,%2,%3;" : "=l"(d) : "l"(a), "l"(b), "l"(c));
    return d;
}
static __device__ __forceinline__ unsigned long long add2(unsigned long long a,
                                                           unsigned long long b) {
    unsigned long long d;
    asm("add.rn.f32x2 %0,%1,%2;" : "=l"(d) : "l"(a), "l"(b));
    return d;
}
static __device__ __forceinline__ unsigned long long mul2(unsigned long long a,
                                                           unsigned long long b) {
    unsigned long long d;
    asm("mul.rn.f32x2 %0,%1,%2;" : "=l"(d) : "l"(a), "l"(b));
    return d;
}

static constexpr int Bb = 256;
static constexpr int Tt = 2048;
static constexpr int Dd = 64;
static constexpr int NW = 4;    // warps per batch
static constexpr int NT = 128;  // threads per block
static constexpr int CH = 8;    // timesteps per staged chunk
static constexpr int NCH = Tt / CH;  // 256 chunks

// One block (4 warps) per batch element. Lane l owns output columns (2l, 2l+1)
// packed f32x2; warp w owns the reduction slice d' in [16w, 16w+16).
// State in LINEAR domain with power-of-two renormalization:
//   v_t[d] = exp(alpha_t[d]) * 2^{-K_t}, K accumulated in integer ktot.
__global__ __launch_bounds__(NT) void crf_forward_kernel(
    const float* __restrict__ p,       // [B,T,D]
    const int*   __restrict__ y,       // [B,T,D] one-hot
    const int*   __restrict__ mask,    // [B,T]   1 = padding
    const float* __restrict__ trans,   // [D,D]
    float*       __restrict__ out)     // [B]
{
    const int b   = blockIdx.x;
    const int tid = threadIdx.x;
    const int w   = tid >> 5;
    const int l   = tid & 31;

    __shared__ unsigned long long part[2][NT];      // per-warp partial sums (double buf)
    __shared__ unsigned long long vdup[NW][16];     // warp-private duplicated state slice
    __shared__ float sp[2][CH][Dd];                 // staged p chunks
    __shared__ int   sy[2][CH][Dd];                 // staged y chunks

    // ---- sequence length L = T - sum(mask[b,:]) (per-warp redundant) ----
    const int4* m4 = reinterpret_cast<const int4*>(mask + (size_t)b * Tt);
    int s = 0;
#pragma unroll
    for (int j = 0; j < 16; j++) {
        int4 v = m4[l + 32 * j];
        s += v.x + v.y + v.z + v.w;
    }
#pragma unroll
    for (int o = 16; o > 0; o >>= 1) s += __shfl_xor_sync(FULL, s, o);
    const int L = Tt - s;

    // ---- expT rows [16w,16w+16), cols (2l,2l+1), packed in 16 u64 regs ----
    unsigned long long eT[16];
#pragma unroll
    for (int j = 0; j < 16; j++) {
        float2 tv = reinterpret_cast<const float2*>(trans)[(16 * w + j) * 32 + l];
        eT[j] = pk2(__expf(tv.x), __expf(tv.y));
    }

    const float4* p4 = reinterpret_cast<const float4*>(p + (size_t)b * Tt * Dd);
    const int4*   y4 = reinterpret_cast<const int4*>(y + (size_t)b * Tt * Dd);

    // ---- stage chunks 0,1 into shared; prefetch chunk 2 into registers ----
    {
        float4 pa = p4[tid], pb = p4[NT + tid];
        int4   ya = y4[tid], yb = y4[NT + tid];
        reinterpret_cast<float4*>(sp[0])[tid] = pa;
        reinterpret_cast<float4*>(sp[1])[tid] = pb;
        reinterpret_cast<int4*>(sy[0])[tid]   = ya;
        reinterpret_cast<int4*>(sy[1])[tid]   = yb;
    }
    float4 prf = p4[2 * NT + tid];
    int4   yrf = y4[2 * NT + tid];
    __syncthreads();

    // ---- t = 0 init (every warp rebuilds the full state redundantly) ----
    float2 p0 = *reinterpret_cast<const float2*>(&sp[0][0][2 * l]);
    float vx = __expf(p0.x);
    float vy = __expf(p0.y);
    float s1 = 0.f, s2 = 0.f;
    int prev = 0;
    if (w == 0) {
        int2 y0 = *reinterpret_cast<const int2*>(&sy[0][0][2 * l]);
        if (y0.x) s1 += p0.x;
        if (y0.y) s1 += p0.y;
        unsigned bx = __ballot_sync(FULL, y0.x != 0);
        unsigned by = __ballot_sync(FULL, y0.y != 0);
        prev = bx ? 2 * (__ffs(bx) - 1) : 2 * (__ffs(by) - 1) + 1;
    }
    int ktot = 0;
    int kx = (int)((__float_as_uint(vx) >> 23) & 255) - 127;
    if ((l >> 3) == w) {
        int base = 2 * (l - 8 * w);
        vdup[w][base]     = pk2(vx, vx);
        vdup[w][base + 1] = pk2(vy, vy);
    }
    __syncwarp();

    for (int t = 1; t < L; t++) {
        const int ch = t >> 3, tb = t & 7, cb = ch & 1;

        // chunk boundary: commit held regs (chunk ch+1), fetch chunk ch+2
        if (tb == 0) {
            reinterpret_cast<float4*>(sp[cb ^ 1])[tid] = prf;
            reinterpret_cast<int4*>(sy[cb ^ 1])[tid]   = yrf;
            int nc = min(ch + 2, NCH - 1);
            prf = p4[nc * NT + tid];
            yrf = y4[nc * NT + tid];
        }

        float2 pt = *reinterpret_cast<const float2*>(&sp[cb][tb][2 * l]);

        // stale exponent correction folded into exp(p_t)
        int k = __shfl_sync(FULL, kx, 0);
        ktot += k;
        float sc = __uint_as_float((unsigned)(127 - k) << 23);  // 2^{-k}
        unsigned long long ep2 = pk2(__expf(pt.x) * sc, __expf(pt.y) * sc);

        // emission / transition scores (warp 0 only)
        if (w == 0) {
            int2 yt = *reinterpret_cast<const int2*>(&sy[cb][tb][2 * l]);
            if (yt.x) s1 += pt.x;
            if (yt.y) s1 += pt.y;
            unsigned bbx = __ballot_sync(FULL, yt.x != 0);
            unsigned bby = __ballot_sync(FULL, yt.y != 0);
            int cur = bbx ? 2 * (__ffs(bbx) - 1) : 2 * (__ffs(bby) - 1) + 1;
            if (l == 0) s2 += trans[prev * 64 + cur];
            prev = cur;
        }

        // partial matvec over this warp's 16 source rows
        unsigned long long a0 = 0, a1 = 0, a2 = 0, a3 = 0;
#pragma unroll
        for (int j = 0; j < 16; j += 4) {
            a0 = fma2(vdup[w][j + 0], eT[j + 0], a0);
            a1 = fma2(vdup[w][j + 1], eT[j + 1], a1);
            a2 = fma2(vdup[w][j + 2], eT[j + 2], a2);
            a3 = fma2(vdup[w][j + 3], eT[j + 3], a3);
        }
        part[t & 1][tid] = add2(add2(a0, a1), add2(a2, a3));
        __syncthreads();

        // every warp redundantly combines the 4 partials -> full new state
        unsigned long long S = add2(add2(part[t & 1][l],      part[t & 1][32 + l]),
                                    add2(part[t & 1][64 + l], part[t & 1][96 + l]));
        unsigned long long v2 = mul2(S, ep2);
        upk2(v2, vx, vy);
        kx = (int)((__float_as_uint(vx) >> 23) & 255) - 127;

        // re-store this warp's own d'-slice as duplicated pairs
        if ((l >> 3) == w) {
            int base = 2 * (l - 8 * w);
            vdup[w][base]     = pk2(vx, vx);
            vdup[w][base + 1] = pk2(vy, vy);
        }
        __syncwarp();
    }

    // ---- finalize on warp 0: logZ = log(sum v) + ktot*ln2 ----
    if (w == 0) {
        float sumv = vx + vy;
#pragma unroll
        for (int o = 16; o > 0; o >>= 1) {
            sumv += __shfl_xor_sync(FULL, sumv, o);
            s1   += __shfl_xor_sync(FULL, s1, o);
        }
        if (l == 0) {
            out[b] = logf(sumv) + (float)ktot * 0.6931471805599453f - s1 - s2;
        }
    }
}

extern "C" void kernel_launch(void* const* d_in, const int* in_sizes, int n_in,
                              void* d_out, int out_size) {
    const float* p     = (const float*)d_in[0];
    const int*   y     = (const int*)d_in[1];
    const int*   mask  = (const int*)d_in[2];
    const float* trans = (const float*)d_in[3];
    float* out = (float*)d_out;
    crf_forward_kernel<<<Bb, NT>>>(p, y, mask, trans, out);
}